// round 5
// baseline (speedup 1.0000x reference)
#include <cuda_runtime.h>
#include <cuda_bf16.h>
#include <math.h>

// Problem constants
#define B_   8
#define C_   8
#define K_   10
#define D_   512
#define H_   96
#define W_   96
#define HW_  (H_*W_)          // 9216
#define NPIX (B_*HW_)         // 73728
#define DS_  2                // d splits
#define DPS_ 256              // d per split

// ---------------- scratch (__device__ globals; no allocations) ----------------
// prototypes packed: g_P2[d2][c*20 + k*2 + parity], row stride 160 floats
__device__ __align__(16) float g_P2[256 * 160];                     // 160 KB
__device__ __align__(16) float g_part[(size_t)DS_ * NPIX * 12];     // 7.1 MB partial dots
__device__ __align__(16) float g_S[(size_t)NPIX * 12];              // 3.5 MB normalized sims
__device__ float g_MomSeg[64 * 8 * 66];                             // per-(bc,seg) moments
__device__ int   g_cnt[64];                                         // class pixel counts per (b,c)

__constant__ int cPK[45] = {0,0,0,0,0,0,0,0,0, 1,1,1,1,1,1,1,1, 2,2,2,2,2,2,2,
                            3,3,3,3,3,3, 4,4,4,4,4, 5,5,5,5, 6,6,6, 7,7, 8};
__constant__ int cPL[45] = {1,2,3,4,5,6,7,8,9, 2,3,4,5,6,7,8,9, 3,4,5,6,7,8,9,
                            4,5,6,7,8,9, 5,6,7,8,9, 6,7,8,9, 7,8,9, 8,9, 9};

// ---- f32x2 packed helpers ----
__device__ __forceinline__ unsigned long long pk2(float a, float b) {
    unsigned long long r;
    asm("mov.b64 %0, {%1, %2};" : "=l"(r) : "f"(a), "f"(b));
    return r;
}
__device__ __forceinline__ void ffma2(unsigned long long& d, unsigned long long a, unsigned long long b) {
    asm("fma.rn.f32x2 %0, %1, %2, %0;" : "+l"(d) : "l"(a), "l"(b));
}
__device__ __forceinline__ float upsum(unsigned long long v) {
    float lo, hi;
    asm("mov.b64 {%0, %1}, %2;" : "=f"(lo), "=f"(hi) : "l"(v));
    return lo + hi;
}

// ---------------- k0: normalize prototypes into packed layout + zero g_cnt ----------------
__global__ void k0_norm_proto(const float* __restrict__ P) {
    int blk = blockIdx.x;
    int tid = threadIdx.x;          // 128
    if (blk == 80) {
        if (tid < 64) g_cnt[tid] = 0;
        return;
    }
    const float* row = P + blk * D_;
    float ss = 0.f;
    for (int i = tid; i < D_; i += 128) { float v = row[i]; ss = fmaf(v, v, ss); }
    #pragma unroll
    for (int o = 16; o; o >>= 1) ss += __shfl_xor_sync(0xffffffffu, ss, o);
    __shared__ float red[4];
    if ((tid & 31) == 0) red[tid >> 5] = ss;
    __syncthreads();
    float tot = red[0] + red[1] + red[2] + red[3];
    float inv = 1.0f / fmaxf(sqrtf(tot), 1e-12f);
    int c = blk / K_, k = blk % K_;
    for (int d = tid; d < D_; d += 128)
        g_P2[(d >> 1) * 160 + c * 20 + k * 2 + (d & 1)] = row[d] * inv;
}

// ---------------- k1: partial sims over a 256-d slice (FFMA2 packed) ----------------
// grid = 512: blk = ds*256 + (b*32 + rowtriple); block = 288 threads = 3 rows.
__global__ __launch_bounds__(288) void k1_sim(const float* __restrict__ F,
                                              const int* __restrict__ mask) {
    __shared__ __align__(16) float sp[32 * 160];   // 20 KB: 32 d2-rows of packed protos

    int tid = threadIdx.x;
    int blk = blockIdx.x;
    int ds  = blk >> 8;
    int sub = blk & 255;
    int b = sub >> 5;
    int row0 = (sub & 31) * 3;
    int pin  = row0 * W_ + tid;
    int pixg = b * HW_ + pin;

    int m = mask[pixg];
    int c = (m > 0) ? (m - 1) : 0;

    const float* fb = F + ((size_t)b * D_ + ds * DPS_) * HW_ + pin;

    unsigned long long n2 = 0ull;
    unsigned long long s2[10];
    #pragma unroll
    for (int k = 0; k < 10; k++) s2[k] = 0ull;

    for (int ch = 0; ch < 4; ch++) {
        __syncthreads();
        const float4* src = (const float4*)(g_P2 + (size_t)(ds * 128 + ch * 32) * 160);
        float4* dst = (float4*)sp;
        for (int i = tid; i < 32 * 160 / 4; i += 288) dst[i] = src[i];
        __syncthreads();

        const float* fp = fb + (size_t)ch * 64 * HW_;
        #pragma unroll 2
        for (int i2 = 0; i2 < 32; i2 += 4) {
            float f[8];
            #pragma unroll
            for (int j = 0; j < 8; j++) f[j] = fp[(size_t)(i2 * 2 + j) * HW_];
            #pragma unroll
            for (int j2 = 0; j2 < 4; j2++) {
                unsigned long long f2 = pk2(f[2 * j2], f[2 * j2 + 1]);
                const ulonglong2* q = (const ulonglong2*)(sp + (i2 + j2) * 160 + c * 20);
                ulonglong2 q0 = q[0], q1 = q[1], q2 = q[2], q3 = q[3], q4 = q[4];
                ffma2(n2, f2, f2);
                ffma2(s2[0], f2, q0.x); ffma2(s2[1], f2, q0.y);
                ffma2(s2[2], f2, q1.x); ffma2(s2[3], f2, q1.y);
                ffma2(s2[4], f2, q2.x); ffma2(s2[5], f2, q2.y);
                ffma2(s2[6], f2, q3.x); ffma2(s2[7], f2, q3.y);
                ffma2(s2[8], f2, q4.x); ffma2(s2[9], f2, q4.y);
            }
        }
    }
    float4* o = (float4*)(g_part + ((size_t)ds * NPIX + pixg) * 12);
    o[0] = make_float4(upsum(s2[0]), upsum(s2[1]), upsum(s2[2]), upsum(s2[3]));
    o[1] = make_float4(upsum(s2[4]), upsum(s2[5]), upsum(s2[6]), upsum(s2[7]));
    o[2] = make_float4(upsum(s2[8]), upsum(s2[9]), upsum(n2), 0.f);
}

// ---------------- k1m: merge 2 partials + normalize + hist ----------------
// grid = 768 (b*H + h); block = 96 threads (one per w).
__global__ __launch_bounds__(96) void k1m(const int* __restrict__ mask) {
    __shared__ int hist[8];
    int bh = blockIdx.x;
    int b = bh / H_;
    int w = threadIdx.x;
    int pixg = bh * W_ + w;           // == b*HW_ + h*W_ + w

    if (w < 8) hist[w] = 0;
    int m = mask[pixg];
    __syncthreads();
    if (m > 0) atomicAdd(&hist[m - 1], 1);

    const float4* p0 = (const float4*)(g_part + (size_t)pixg * 12);
    const float4* p1 = (const float4*)(g_part + ((size_t)NPIX + pixg) * 12);
    float4 a0 = p0[0], a1 = p0[1], a2 = p0[2];
    float4 b0 = p1[0], b1 = p1[1], b2 = p1[2];
    a0.x += b0.x; a0.y += b0.y; a0.z += b0.z; a0.w += b0.w;
    a1.x += b1.x; a1.y += b1.y; a1.z += b1.z; a1.w += b1.w;
    a2.x += b2.x; a2.y += b2.y; a2.z += b2.z;
    float inv = 1.0f / fmaxf(sqrtf(a2.z), 1e-12f);
    float4* o = (float4*)(g_S + (size_t)pixg * 12);
    o[0] = make_float4(a0.x * inv, a0.y * inv, a0.z * inv, a0.w * inv);
    o[1] = make_float4(a1.x * inv, a1.y * inv, a1.z * inv, a1.w * inv);
    o[2] = make_float4(a2.x * inv, a2.y * inv, 0.f, 0.f);

    __syncthreads();
    if (w < 8) atomicAdd(&g_cnt[b * 8 + w], hist[w]);
}

// ---------------- k2: fused horiz+vert 7-tap pool + region + moments ----------------
// grid = 512: blk = bc*8 + seg (stripe of 12 rows); block = 96 threads (one per w).
__global__ __launch_bounds__(96) void k2_fused(const int* __restrict__ mask) {
    __shared__ __align__(16) float ring[7][96 * 12];   // pooled rows      32.2 KB
    __shared__ __align__(16) float rowS[2][96 * 12];   // raw S rows (dbl)  9.2 KB
    __shared__ int rmask[2][96];

    int blk = blockIdx.x;
    int bc  = blk >> 3;                 // b*8 + c
    int seg = blk & 7;
    int b = bc >> 3, c = bc & 7;
    int w = threadIdx.x;
    int h0 = seg * 12;

    float vs[11];
    #pragma unroll
    for (int i = 0; i < 11; i++) vs[i] = 0.f;
    float V = 0.f;
    float Sr[10]; float M[55];
    #pragma unroll
    for (int k = 0; k < 10; k++) Sr[k] = 0.f;
    #pragma unroll
    for (int i = 0; i < 55; i++) M[i] = 0.f;

    for (int hh = h0 - 3; hh < h0 + 15; hh++) {
        int buf = hh & 1;
        bool inb = (hh >= 0 && hh < 96);
        if (inb) {
            const float4* src = (const float4*)(g_S + (size_t)(b * HW_ + hh * W_ + w) * 12);
            float4* dst = (float4*)(rowS[buf] + w * 12);
            dst[0] = src[0]; dst[1] = src[1]; dst[2] = src[2];
            rmask[buf][w] = mask[b * HW_ + hh * W_ + w];
        }
        __syncthreads();

        // horizontal masked 7-tap at (hh, w) for class c
        float p[11];
        #pragma unroll
        for (int i = 0; i < 11; i++) p[i] = 0.f;
        if (inb) {
            #pragma unroll
            for (int dw = -3; dw <= 3; dw++) {
                int ww = w + dw;
                if ((unsigned)ww < 96u && rmask[buf][ww] == c + 1) {
                    const float4* sv = (const float4*)(rowS[buf] + ww * 12);
                    float4 x = sv[0], y = sv[1], z = sv[2];
                    p[0]+=x.x; p[1]+=x.y; p[2]+=x.z; p[3]+=x.w;
                    p[4]+=y.x; p[5]+=y.y; p[6]+=y.z; p[7]+=y.w;
                    p[8]+=z.x; p[9]+=z.y; p[10]+=1.f;
                }
            }
        }
        // store into ring (own w only) and add to sliding vertical sum
        float* rg = ring[(hh + 7) % 7] + w * 12;
        #pragma unroll
        for (int i = 0; i < 11; i++) { rg[i] = p[i]; vs[i] += p[i]; }

        int ho = hh - 3;
        if (ho >= h0 && ho < h0 + 12) {
            float den = vs[10] * (1.0f / 49.0f);
            if (den > 0.05f) {
                float inv = 1.0f / (den + 1e-8f);
                float r[10];
                #pragma unroll
                for (int k = 0; k < 10; k++) r[k] = (vs[k] * (1.0f / 49.0f)) * inv;
                V += 1.f;
                #pragma unroll
                for (int k = 0; k < 10; k++) Sr[k] += r[k];
                int idx = 0;
                #pragma unroll
                for (int k = 0; k < 10; k++)
                    #pragma unroll
                    for (int l = k; l < 10; l++) { M[idx] = fmaf(r[k], r[l], M[idx]); idx++; }
            }
            // retire row leaving the window
            const float* rs = ring[(ho - 3 + 7) % 7] + w * 12;
            #pragma unroll
            for (int i = 0; i < 11; i++) vs[i] -= rs[i];
        }
    }

    // warp butterfly reduce (3 warps)
    #pragma unroll
    for (int o = 16; o; o >>= 1) V += __shfl_xor_sync(0xffffffffu, V, o);
    #pragma unroll
    for (int k = 0; k < 10; k++) {
        float v = Sr[k];
        #pragma unroll
        for (int o = 16; o; o >>= 1) v += __shfl_xor_sync(0xffffffffu, v, o);
        Sr[k] = v;
    }
    #pragma unroll
    for (int i = 0; i < 55; i++) {
        float v = M[i];
        #pragma unroll
        for (int o = 16; o; o >>= 1) v += __shfl_xor_sync(0xffffffffu, v, o);
        M[i] = v;
    }
    __shared__ float red[3][66];
    int lane = w & 31, wid = w >> 5;
    if (lane == 0) {
        red[wid][0] = V;
        #pragma unroll
        for (int k = 0; k < 10; k++) red[wid][1 + k] = Sr[k];
        #pragma unroll
        for (int i = 0; i < 55; i++) red[wid][11 + i] = M[i];
    }
    __syncthreads();
    if (w < 66)
        g_MomSeg[(size_t)blk * 66 + w] = red[0][w] + red[1][w] + red[2][w];
}

// ---------------- k3: finalize scalar (1 block, 32 warps; warp per 2 bc) ----------------
__global__ __launch_bounds__(1024) void k3(float* __restrict__ out) {
    __shared__ float sM[64][66];
    __shared__ float sla[64], saf[64];
    int tid = threadIdx.x;
    int wi = tid >> 5, lane = tid & 31;

    #pragma unroll
    for (int t = wi * 2; t < wi * 2 + 2; t++) {
        for (int i = lane; i < 66; i += 32) {
            float s = 0.f;
            #pragma unroll
            for (int seg = 0; seg < 8; seg++) s += g_MomSeg[(size_t)(t * 8 + seg) * 66 + i];
            sM[t][i] = s;
        }
        __syncwarp();
        const float* mm = sM[t];
        float V = mm[0];
        float Vf = fmaxf(V, 1.0f);
        float invVf = 1.0f / Vf;

        float Srk = 0.f, nk = 0.f;
        if (lane < 10) {
            Srk = mm[1 + lane];
            int di = 10 * lane - lane * (lane - 1) / 2;
            float cv = mm[11 + di] - Srk * Srk * invVf;
            nk = sqrtf(fmaxf(cv, 0.f));
        }
        float Sr[10], n[10];
        #pragma unroll
        for (int k = 0; k < 10; k++) {
            Sr[k] = __shfl_sync(0xffffffffu, Srk, k);
            n[k]  = __shfl_sync(0xffffffffu, nk, k);
        }
        float acci = 0.f;
        #pragma unroll
        for (int rep = 0; rep < 2; rep++) {
            int p = lane + rep * 32;
            if (p < 45) {
                int k = cPK[p], l = cPL[p];
                int idx = 10 * k - k * (k - 1) / 2 + (l - k);
                float cv = mm[11 + idx] - Sr[k] * Sr[l] * invVf;
                float g = cv / ((n[k] + 1e-8f) * (n[l] + 1e-8f)) * invVf;
                acci += 2.0f * g * g;
            }
        }
        #pragma unroll
        for (int o = 16; o; o >>= 1) acci += __shfl_xor_sync(0xffffffffu, acci, o);
        if (lane == 0) {
            float loss = acci * (1.0f / 90.0f);
            int cc = g_cnt[t];
            float act = (cc >= 1 && V >= 2.0f) ? 1.0f : 0.0f;
            sla[t] = loss * act;
            saf[t] = act;
        }
        __syncwarp();
    }
    __syncthreads();
    if (tid == 0) {
        float s = 0.f;
        #pragma unroll
        for (int b = 0; b < 8; b++) {
            float la = 0.f, af = 0.f;
            #pragma unroll
            for (int c = 0; c < 8; c++) { la += sla[b * 8 + c]; af += saf[b * 8 + c]; }
            s += la / fmaxf(af, 1.0f);
        }
        out[0] = s * 0.125f;
    }
}

// ---------------- launch ----------------
extern "C" void kernel_launch(void* const* d_in, const int* in_sizes, int n_in,
                              void* d_out, int out_size) {
    const float* F  = (const float*)d_in[0];   // feature_map [8,512,96,96]
    const float* P  = (const float*)d_in[1];   // prototypes  [80,512]
    const int*   Mk = (const int*)d_in[2];     // pseudo_mask [8,96,96]
    float* out = (float*)d_out;

    k0_norm_proto<<<81, 128>>>(P);
    k1_sim<<<512, 288>>>(F, Mk);
    k1m<<<768, 96>>>(Mk);
    k2_fused<<<512, 96>>>(Mk);
    k3<<<1, 1024>>>(out);
}